// round 3
// baseline (speedup 1.0000x reference)
#include <cuda_runtime.h>

#define NN 100000
#define EE 800000
#define DD 128

// ---------------- static device scratch (no allocations allowed) ----------------
__device__ float g_hs[NN * DD];      // scaled node features (input to aggregation)
__device__ float g_agg[NN * DD];     // aggregated (and norm_in-scaled) features
__device__ int   g_deg_out[NN];
__device__ int   g_deg_in[NN];
__device__ float g_norm_out[NN];
__device__ float g_norm_in[NN];
__device__ int   g_row_ptr[NN + 1];  // CSR by dst
__device__ int   g_fill[NN];
__device__ int   g_col[EE];          // src index per CSR slot
__device__ int   g_part[256];        // scan partials
__device__ float g_colsum[DD];       // column sums of final h (for mean)

// ---------------- helpers ----------------
__device__ __forceinline__ float4 f4_add(float4 a, float4 b) {
    return make_float4(a.x + b.x, a.y + b.y, a.z + b.z, a.w + b.w);
}
__device__ __forceinline__ float4 f4_scale(float4 a, float s) {
    return make_float4(a.x * s, a.y * s, a.z * s, a.w * s);
}

// ---------------- preprocessing kernels ----------------
__global__ void k_zero(int n) {
    int i = blockIdx.x * blockDim.x + threadIdx.x;
    if (i < n) { g_deg_out[i] = 0; g_deg_in[i] = 0; g_fill[i] = 0; }
    if (i < DD) g_colsum[i] = 0.0f;
}

__global__ void k_degrees(const int* __restrict__ src, const int* __restrict__ dst, int e) {
    int i = blockIdx.x * blockDim.x + threadIdx.x;
    if (i < e) {
        atomicAdd(&g_deg_out[src[i]], 1);
        atomicAdd(&g_deg_in[dst[i]], 1);
    }
}

__global__ void k_norms(int n) {
    int i = blockIdx.x * blockDim.x + threadIdx.x;
    if (i < n) {
        g_norm_out[i] = rsqrtf(fmaxf((float)g_deg_out[i], 1.0f));
        g_norm_in[i]  = rsqrtf(fmaxf((float)g_deg_in[i], 1.0f));
    }
}

// --- 3-kernel exclusive scan of g_deg_in -> g_row_ptr ---
__global__ void k_scan_partial(int n) {
    int idx = blockIdx.x * 1024 + threadIdx.x;
    int v = (idx < n) ? g_deg_in[idx] : 0;
    #pragma unroll
    for (int o = 16; o > 0; o >>= 1) v += __shfl_down_sync(0xFFFFFFFFu, v, o);
    __shared__ int ws[32];
    if ((threadIdx.x & 31) == 0) ws[threadIdx.x >> 5] = v;
    __syncthreads();
    if (threadIdx.x < 32) {
        int s = ws[threadIdx.x];
        #pragma unroll
        for (int o = 16; o > 0; o >>= 1) s += __shfl_down_sync(0xFFFFFFFFu, s, o);
        if (threadIdx.x == 0) g_part[blockIdx.x] = s;
    }
}

__global__ void k_scan_mid(int nchunk, int n) {
    // single thread: scan the (<=98) chunk partials
    int sum = 0;
    for (int i = 0; i < nchunk; i++) {
        int v = g_part[i];
        g_part[i] = sum;
        sum += v;
    }
    g_row_ptr[n] = sum;  // == E
}

__global__ void k_scan_final(int n) {
    int idx = blockIdx.x * 1024 + threadIdx.x;
    int v = (idx < n) ? g_deg_in[idx] : 0;
    int lane = threadIdx.x & 31, wid = threadIdx.x >> 5;
    int inc = v;
    #pragma unroll
    for (int o = 1; o < 32; o <<= 1) {
        int t = __shfl_up_sync(0xFFFFFFFFu, inc, o);
        if (lane >= o) inc += t;
    }
    __shared__ int ws[32];
    if (lane == 31) ws[wid] = inc;
    __syncthreads();
    if (wid == 0) {
        int s = ws[lane];
        #pragma unroll
        for (int o = 1; o < 32; o <<= 1) {
            int t = __shfl_up_sync(0xFFFFFFFFu, s, o);
            if (lane >= o) s += t;
        }
        ws[lane] = s;
    }
    __syncthreads();
    int add = (wid > 0) ? ws[wid - 1] : 0;
    if (idx < n) g_row_ptr[idx] = (inc - v) + add + g_part[blockIdx.x];
}

__global__ void k_csr_fill(const int* __restrict__ src, const int* __restrict__ dst, int e) {
    int i = blockIdx.x * blockDim.x + threadIdx.x;
    if (i < e) {
        int d = dst[i];
        int pos = g_row_ptr[d] + atomicAdd(&g_fill[d], 1);
        g_col[pos] = src[i];
    }
}

// hs0 = feature * norm_out[row]
__global__ void k_scale_input(const float4* __restrict__ feat, int n4) {
    int i = blockIdx.x * blockDim.x + threadIdx.x;
    if (i < n4) {
        int row = i >> 5;  // 32 float4 per row
        float s = g_norm_out[row];
        ((float4*)g_hs)[i] = f4_scale(feat[i], s);
    }
}

// ---------------- aggregation: one warp per node (gather, no float atomics) ----------------
__global__ void __launch_bounds__(256) k_aggregate(int n) {
    int warp = (blockIdx.x * blockDim.x + threadIdx.x) >> 5;
    int lane = threadIdx.x & 31;
    if (warp >= n) return;
    const float4* __restrict__ hs4 = (const float4*)g_hs;
    int beg = g_row_ptr[warp];
    int end = g_row_ptr[warp + 1];
    float4 acc = make_float4(0.f, 0.f, 0.f, 0.f);
    int e = beg;
    // 4-deep unroll for MLP
    for (; e + 4 <= end; e += 4) {
        int s0 = g_col[e], s1 = g_col[e + 1], s2 = g_col[e + 2], s3 = g_col[e + 3];
        float4 v0 = hs4[(size_t)s0 * 32 + lane];
        float4 v1 = hs4[(size_t)s1 * 32 + lane];
        float4 v2 = hs4[(size_t)s2 * 32 + lane];
        float4 v3 = hs4[(size_t)s3 * 32 + lane];
        acc = f4_add(acc, f4_add(f4_add(v0, v1), f4_add(v2, v3)));
    }
    for (; e < end; e++) {
        acc = f4_add(acc, hs4[(size_t)g_col[e] * 32 + lane]);
    }
    float ni = g_norm_in[warp];
    ((float4*)g_agg)[(size_t)warp * 32 + lane] = f4_scale(acc, ni);
}

// ---------------- GEMM: out = relu(g_agg @ W + b) [* norm_out | + colsum partials] ----------------
// Block: 128 rows x 128 cols, 256 threads (16x16), 8x8 per-thread tile with
// split-4 row/col groups (ty*4 and 64+ty*4) for conflict-free LDS.128.
__global__ void __launch_bounds__(256) k_gemm(
    const float* __restrict__ W, const float* __restrict__ bias,
    float* __restrict__ out, int M, int last_layer)
{
    __shared__ __align__(16) float As[16][128];
    __shared__ __align__(16) float Ws[16][128];

    int tid = threadIdx.x;
    int tx = tid & 15, ty = tid >> 4;
    int row0 = blockIdx.x * 128;
    const float* __restrict__ A = g_agg;

    float acc[8][8];
    #pragma unroll
    for (int i = 0; i < 8; i++)
        #pragma unroll
        for (int j = 0; j < 8; j++) acc[i][j] = 0.0f;

    for (int kc = 0; kc < DD; kc += 16) {
        // load A chunk (transposed into As[k][row])
        #pragma unroll
        for (int li = 0; li < 2; li++) {
            int i = tid + li * 256;      // 0..511 float4
            int r = i >> 2;              // 0..127
            int k4 = (i & 3) * 4;        // 0,4,8,12
            int grow = row0 + r;
            float4 v = make_float4(0.f, 0.f, 0.f, 0.f);
            if (grow < M) v = *(const float4*)(A + (size_t)grow * DD + kc + k4);
            As[k4 + 0][r] = v.x;
            As[k4 + 1][r] = v.y;
            As[k4 + 2][r] = v.z;
            As[k4 + 3][r] = v.w;
        }
        // load W chunk (natural layout Ws[k][n])
        #pragma unroll
        for (int li = 0; li < 2; li++) {
            int i = tid + li * 256;      // 0..511 float4
            int k = i >> 5;              // 0..15
            int nn = (i & 31) * 4;
            *(float4*)&Ws[k][nn] = *(const float4*)(W + (size_t)(kc + k) * DD + nn);
        }
        __syncthreads();
        #pragma unroll
        for (int k = 0; k < 16; k++) {
            float a[8], w[8];
            *(float4*)(a)     = *(const float4*)&As[k][ty * 4];
            *(float4*)(a + 4) = *(const float4*)&As[k][ty * 4 + 64];
            *(float4*)(w)     = *(const float4*)&Ws[k][tx * 4];
            *(float4*)(w + 4) = *(const float4*)&Ws[k][tx * 4 + 64];
            #pragma unroll
            for (int i = 0; i < 8; i++)
                #pragma unroll
                for (int j = 0; j < 8; j++)
                    acc[i][j] += a[i] * w[j];
        }
        __syncthreads();
    }

    // bias for this thread's 8 columns
    float b[8];
    *(float4*)(b)     = *(const float4*)(bias + tx * 4);
    *(float4*)(b + 4) = *(const float4*)(bias + tx * 4 + 64);

    int c0 = tx * 4, c1 = tx * 4 + 64;

    if (!last_layer) {
        // out = relu(acc + b) * norm_out[row]  -> g_hs (next layer's scaled input)
        #pragma unroll
        for (int i = 0; i < 8; i++) {
            int r = (i < 4) ? (ty * 4 + i) : (64 + ty * 4 + (i - 4));
            int grow = row0 + r;
            if (grow < M) {
                float s = g_norm_out[grow];
                float4 o0, o1;
                o0.x = fmaxf(acc[i][0] + b[0], 0.f) * s;
                o0.y = fmaxf(acc[i][1] + b[1], 0.f) * s;
                o0.z = fmaxf(acc[i][2] + b[2], 0.f) * s;
                o0.w = fmaxf(acc[i][3] + b[3], 0.f) * s;
                o1.x = fmaxf(acc[i][4] + b[4], 0.f) * s;
                o1.y = fmaxf(acc[i][5] + b[5], 0.f) * s;
                o1.z = fmaxf(acc[i][6] + b[6], 0.f) * s;
                o1.w = fmaxf(acc[i][7] + b[7], 0.f) * s;
                *(float4*)(g_hs + (size_t)grow * DD + c0) = o0;
                *(float4*)(g_hs + (size_t)grow * DD + c1) = o1;
            }
        }
    } else {
        // final layer: out = relu(acc + b) -> d_out, plus column-sum partials for mean
        float colpart[8];
        #pragma unroll
        for (int j = 0; j < 8; j++) colpart[j] = 0.0f;
        #pragma unroll
        for (int i = 0; i < 8; i++) {
            int r = (i < 4) ? (ty * 4 + i) : (64 + ty * 4 + (i - 4));
            int grow = row0 + r;
            if (grow < M) {
                float v[8];
                #pragma unroll
                for (int j = 0; j < 8; j++) {
                    v[j] = fmaxf(acc[i][j] + b[j], 0.f);
                    colpart[j] += v[j];
                }
                *(float4*)(out + (size_t)grow * DD + c0) = make_float4(v[0], v[1], v[2], v[3]);
                *(float4*)(out + (size_t)grow * DD + c1) = make_float4(v[4], v[5], v[6], v[7]);
            }
        }
        // block-level column reduction in smem (reuse As), then 128 atomics/block
        __syncthreads();
        #pragma unroll
        for (int j = 0; j < 4; j++) {
            As[ty][c0 + j] = colpart[j];
            As[ty][c1 + j] = colpart[4 + j];
        }
        __syncthreads();
        if (tid < 128) {
            float s = 0.0f;
            #pragma unroll
            for (int t = 0; t < 16; t++) s += As[t][tid];
            atomicAdd(&g_colsum[tid], s);
        }
    }
}

__global__ void k_mean(float* __restrict__ out_hg, float inv_n) {
    int i = threadIdx.x;
    if (i < DD) out_hg[i] = g_colsum[i] * inv_n;
}

// ---------------- launch ----------------
extern "C" void kernel_launch(void* const* d_in, const int* in_sizes, int n_in,
                              void* d_out, int out_size) {
    const float* feature = (const float*)d_in[0];
    const int*   src     = (const int*)d_in[1];
    const int*   dst     = (const int*)d_in[2];
    const float* W1 = (const float*)d_in[3];
    const float* b1 = (const float*)d_in[4];
    const float* W2 = (const float*)d_in[5];
    const float* b2 = (const float*)d_in[6];
    const float* W3 = (const float*)d_in[7];
    const float* b3 = (const float*)d_in[8];
    float* out = (float*)d_out;

    int N = in_sizes[0] / DD;   // 100000
    int E = in_sizes[1];        // 800000

    int gN   = (N + 255) / 256;
    int gE   = (E + 255) / 256;
    int nchunk = (N + 1023) / 1024;
    int gEl  = (N * 32 + 255) / 256;     // elementwise over N*32 float4
    int gAgg = (N * 32 + 255) / 256;     // one warp per node
    int gGemm = (N + 127) / 128;

    // preprocessing
    k_zero<<<gN, 256>>>(N);
    k_degrees<<<gE, 256>>>(src, dst, E);
    k_norms<<<gN, 256>>>(N);
    k_scan_partial<<<nchunk, 1024>>>(N);
    k_scan_mid<<<1, 1>>>(nchunk, N);
    k_scan_final<<<nchunk, 1024>>>(N);
    k_csr_fill<<<gE, 256>>>(src, dst, E);

    // layer 0 input scaling
    k_scale_input<<<gEl, 256>>>((const float4*)feature, N * 32);

    // layer 1
    k_aggregate<<<gAgg, 256>>>(N);
    k_gemm<<<gGemm, 256>>>(W1, b1, nullptr, N, 0);
    // layer 2
    k_aggregate<<<gAgg, 256>>>(N);
    k_gemm<<<gGemm, 256>>>(W2, b2, nullptr, N, 0);
    // layer 3 (writes h to d_out + column sums)
    k_aggregate<<<gAgg, 256>>>(N);
    k_gemm<<<gGemm, 256>>>(W3, b3, out, N, 1);

    // readout: hg = mean(h, axis=0) appended after h
    if (out_size >= N * DD + DD) {
        k_mean<<<1, 128>>>(out + (size_t)N * DD, 1.0f / (float)N);
    }
}

// round 9
// speedup vs baseline: 1.0148x; 1.0148x over previous
#include <cuda_runtime.h>
#include <cuda_bf16.h>
#include <mma.h>

using namespace nvcuda;

#define NN 100000
#define NPAD 100096              // 782 * 128
#define EE 800000
#define DD 128
#define KEXT 160                 // 128 K + 32 bias/zero block (col 128 of A == 1)

// ---------------- static device scratch (no allocations allowed) ----------------
__device__ float g_h[NPAD * DD];            // hidden node features (fp32)
__device__ float g_hfin[NPAD * DD];         // final-layer output scratch (padded)
__device__ __nv_bfloat16 g_Ahi[NN * DD];    // aggregated features, bf16 high part
__device__ __nv_bfloat16 g_Alo[NN * DD];    // aggregated features, bf16 residual
__device__ __nv_bfloat16 g_Whi[3 * KEXT * DD];  // per-layer [K' x N] weights hi (+bias row 128)
__device__ __nv_bfloat16 g_Wlo[3 * KEXT * DD];  // residuals
__device__ int   g_deg_out[NN];
__device__ int   g_deg_in[NN];
__device__ float g_norm_out[NN];
__device__ float g_norm_in[NN];
__device__ int   g_row_ptr[NN + 1];         // CSR by dst
__device__ int   g_fill[NN];
__device__ int   g_col[EE];                 // src index per CSR slot
__device__ int   g_part[256];               // scan partials
__device__ float g_colsum[DD];              // column sums of final h (for mean)

// ---------------- helpers ----------------
__device__ __forceinline__ void f4_fma(float4& acc, float4 v, float s) {
    acc.x = fmaf(v.x, s, acc.x);
    acc.y = fmaf(v.y, s, acc.y);
    acc.z = fmaf(v.z, s, acc.z);
    acc.w = fmaf(v.w, s, acc.w);
}
__device__ __forceinline__ float4 f4_add(float4 a, float4 b) {
    return make_float4(a.x + b.x, a.y + b.y, a.z + b.z, a.w + b.w);
}
__device__ __forceinline__ float4 f4_scale(float4 a, float s) {
    return make_float4(a.x * s, a.y * s, a.z * s, a.w * s);
}

// ---------------- preprocessing kernels ----------------
__global__ void k_zero(int n) {
    int i = blockIdx.x * blockDim.x + threadIdx.x;
    if (i < n) { g_deg_out[i] = 0; g_deg_in[i] = 0; g_fill[i] = 0; }
    if (i < DD) g_colsum[i] = 0.0f;
}

__global__ void k_degrees(const int* __restrict__ src, const int* __restrict__ dst, int e) {
    int i = blockIdx.x * blockDim.x + threadIdx.x;
    if (i < e) {
        atomicAdd(&g_deg_out[src[i]], 1);
        atomicAdd(&g_deg_in[dst[i]], 1);
    }
}

__global__ void k_norms(int n) {
    int i = blockIdx.x * blockDim.x + threadIdx.x;
    if (i < n) {
        g_norm_out[i] = rsqrtf(fmaxf((float)g_deg_out[i], 1.0f));
        g_norm_in[i]  = rsqrtf(fmaxf((float)g_deg_in[i], 1.0f));
    }
}

// --- 3-kernel exclusive scan of g_deg_in -> g_row_ptr ---
__global__ void k_scan_partial(int n) {
    int idx = blockIdx.x * 1024 + threadIdx.x;
    int v = (idx < n) ? g_deg_in[idx] : 0;
    #pragma unroll
    for (int o = 16; o > 0; o >>= 1) v += __shfl_down_sync(0xFFFFFFFFu, v, o);
    __shared__ int ws[32];
    if ((threadIdx.x & 31) == 0) ws[threadIdx.x >> 5] = v;
    __syncthreads();
    if (threadIdx.x < 32) {
        int s = ws[threadIdx.x];
        #pragma unroll
        for (int o = 16; o > 0; o >>= 1) s += __shfl_down_sync(0xFFFFFFFFu, s, o);
        if (threadIdx.x == 0) g_part[blockIdx.x] = s;
    }
}

__global__ void k_scan_mid(int nchunk, int n) {
    int sum = 0;
    for (int i = 0; i < nchunk; i++) {
        int v = g_part[i];
        g_part[i] = sum;
        sum += v;
    }
    g_row_ptr[n] = sum;  // == E
}

__global__ void k_scan_final(int n) {
    int idx = blockIdx.x * 1024 + threadIdx.x;
    int v = (idx < n) ? g_deg_in[idx] : 0;
    int lane = threadIdx.x & 31, wid = threadIdx.x >> 5;
    int inc = v;
    #pragma unroll
    for (int o = 1; o < 32; o <<= 1) {
        int t = __shfl_up_sync(0xFFFFFFFFu, inc, o);
        if (lane >= o) inc += t;
    }
    __shared__ int ws[32];
    if (lane == 31) ws[wid] = inc;
    __syncthreads();
    if (wid == 0) {
        int s = ws[lane];
        #pragma unroll
        for (int o = 1; o < 32; o <<= 1) {
            int t = __shfl_up_sync(0xFFFFFFFFu, s, o);
            if (lane >= o) s += t;
        }
        ws[lane] = s;
    }
    __syncthreads();
    int add = (wid > 0) ? ws[wid - 1] : 0;
    if (idx < n) g_row_ptr[idx] = (inc - v) + add + g_part[blockIdx.x];
}

__global__ void k_csr_fill(const int* __restrict__ src, const int* __restrict__ dst, int e) {
    int i = blockIdx.x * blockDim.x + threadIdx.x;
    if (i < e) {
        int d = dst[i];
        int pos = g_row_ptr[d] + atomicAdd(&g_fill[d], 1);
        g_col[pos] = src[i];
    }
}

// ---------------- W split: fp32 -> bf16 hi + bf16 residual, bias folded as row 128
__global__ void k_split_w(const float* __restrict__ W, const float* __restrict__ bias, int lay) {
    int i = blockIdx.x * blockDim.x + threadIdx.x;
    if (i >= KEXT * DD) return;
    int k = i / DD, n = i % DD;
    float w = (k < DD) ? W[k * DD + n] : ((k == DD) ? bias[n] : 0.0f);
    __nv_bfloat16 hi = __float2bfloat16(w);
    __nv_bfloat16 lo = __float2bfloat16(w - __bfloat162float(hi));
    g_Whi[lay * KEXT * DD + i] = hi;
    g_Wlo[lay * KEXT * DD + i] = lo;
}

// ---------------- aggregation: one warp per node (gather, no float atomics) ----
// acc = sum_e feat[src_e]*norm_out[src_e]; result = acc*norm_in -> bf16 hi/lo split
__global__ void __launch_bounds__(256) k_aggregate(const float4* __restrict__ in, int use_in, int n) {
    int warp = (blockIdx.x * blockDim.x + threadIdx.x) >> 5;
    int lane = threadIdx.x & 31;
    if (warp >= n) return;
    const float4* __restrict__ feat4 = use_in ? in : (const float4*)g_h;
    int beg = g_row_ptr[warp];
    int end = g_row_ptr[warp + 1];
    float4 acc = make_float4(0.f, 0.f, 0.f, 0.f);
    int e = beg;
    for (; e + 4 <= end; e += 4) {
        int s0 = g_col[e], s1 = g_col[e + 1], s2 = g_col[e + 2], s3 = g_col[e + 3];
        float n0 = g_norm_out[s0], n1 = g_norm_out[s1];
        float n2 = g_norm_out[s2], n3 = g_norm_out[s3];
        float4 v0 = feat4[(size_t)s0 * 32 + lane];
        float4 v1 = feat4[(size_t)s1 * 32 + lane];
        float4 v2 = feat4[(size_t)s2 * 32 + lane];
        float4 v3 = feat4[(size_t)s3 * 32 + lane];
        f4_fma(acc, v0, n0);
        f4_fma(acc, v1, n1);
        f4_fma(acc, v2, n2);
        f4_fma(acc, v3, n3);
    }
    for (; e < end; e++) {
        int s = g_col[e];
        f4_fma(acc, feat4[(size_t)s * 32 + lane], g_norm_out[s]);
    }
    float4 r = f4_scale(acc, g_norm_in[warp]);

    // split into bf16 hi + residual lo
    __nv_bfloat16 a0 = __float2bfloat16(r.x), a1 = __float2bfloat16(r.y);
    __nv_bfloat16 a2 = __float2bfloat16(r.z), a3 = __float2bfloat16(r.w);
    __nv_bfloat16 l0 = __float2bfloat16(r.x - __bfloat162float(a0));
    __nv_bfloat16 l1 = __float2bfloat16(r.y - __bfloat162float(a1));
    __nv_bfloat16 l2 = __float2bfloat16(r.z - __bfloat162float(a2));
    __nv_bfloat16 l3 = __float2bfloat16(r.w - __bfloat162float(a3));
    size_t base = (size_t)warp * DD + lane * 4;
    __nv_bfloat162 h01, h23, q01, q23;
    h01.x = a0; h01.y = a1; h23.x = a2; h23.y = a3;
    q01.x = l0; q01.y = l1; q23.x = l2; q23.y = l3;
    *(__nv_bfloat162*)(g_Ahi + base)     = h01;
    *(__nv_bfloat162*)(g_Ahi + base + 2) = h23;
    *(__nv_bfloat162*)(g_Alo + base)     = q01;
    *(__nv_bfloat162*)(g_Alo + base + 2) = q23;
}

// ---------------- GEMM via WMMA bf16-split, fp32 accumulate --------------------
// Block 128x128, 256 threads (8 warps, 2x4), warp tile 64x32 (4x2 wmma frags).
// D = Ah@Wh + Al@Wh + Ah@Wl  (missing Al@Wl term ~2^-18 relative).
// Bias folded as K-block 128..159 (A col 128 == 1). ReLU on fragment elements.
#define SA 40    // Ah_s/Al_s row stride (bf16 elems), 80B: 16B-aligned, pad vs conflicts
#define SW 136   // Wh_s/Wl_s row stride

__global__ void __launch_bounds__(256) k_gemm(int lay, int last, int M) {
    __shared__ __align__(16) __nv_bfloat16 Ah_s[128 * SA];
    __shared__ __align__(16) __nv_bfloat16 Al_s[128 * SA];
    __shared__ __align__(16) __nv_bfloat16 Wh_s[32 * SW];
    __shared__ __align__(16) __nv_bfloat16 Wl_s[32 * SW];

    int tid = threadIdx.x;
    int wid = tid >> 5;
    int warp_m = wid & 1;        // 2 row-groups of 64
    int warp_n = wid >> 1;       // 4 col-groups of 32
    int row0 = blockIdx.x * 128;

    const __nv_bfloat16* __restrict__ Whg = g_Whi + (size_t)lay * KEXT * DD;
    const __nv_bfloat16* __restrict__ Wlg = g_Wlo + (size_t)lay * KEXT * DD;
    float* __restrict__ dst = last ? g_hfin : g_h;

    wmma::fragment<wmma::accumulator, 16, 16, 16, float> acc[4][2];
    #pragma unroll
    for (int m = 0; m < 4; m++)
        #pragma unroll
        for (int n = 0; n < 2; n++)
            wmma::fill_fragment(acc[m][n], 0.0f);

    for (int kc = 0; kc < KEXT; kc += 32) {
        // ---- stage A chunk (128 rows x 32 cols, bf16 hi+lo) ----
        if (kc < DD) {
            #pragma unroll
            for (int li = 0; li < 2; li++) {
                int i = tid + li * 256;      // 0..511, 16B chunks
                int r = i >> 2, q = i & 3;
                int gr = row0 + r;
                uint4 vh = make_uint4(0, 0, 0, 0), vl = make_uint4(0, 0, 0, 0);
                if (gr < M) {
                    vh = *(const uint4*)(g_Ahi + (size_t)gr * DD + kc + q * 8);
                    vl = *(const uint4*)(g_Alo + (size_t)gr * DD + kc + q * 8);
                }
                *(uint4*)(Ah_s + r * SA + q * 8) = vh;
                *(uint4*)(Al_s + r * SA + q * 8) = vl;
            }
        } else {
            // constant block: A col 128 == 1 (bias), rest 0
            __nv_bfloat16 one = __float2bfloat16(1.0f);
            __nv_bfloat16 zer = __float2bfloat16(0.0f);
            for (int i = tid; i < 128 * 32; i += 256) {
                int r = i >> 5, k = i & 31;
                Ah_s[r * SA + k] = (k == 0) ? one : zer;
                Al_s[r * SA + k] = zer;
            }
        }
        // ---- stage W chunk (32 rows x 128 cols) ----
        #pragma unroll
        for (int li = 0; li < 2; li++) {
            int i = tid + li * 256;
            int r = i >> 4, q = i & 15;
            *(uint4*)(Wh_s + r * SW + q * 8) = *(const uint4*)(Whg + (size_t)(kc + r) * DD + q * 8);
            *(uint4*)(Wl_s + r * SW + q * 8) = *(const uint4*)(Wlg + (size_t)(kc + r) * DD + q * 8);
        }
        __syncthreads();

        #pragma unroll
        for (int ks = 0; ks < 2; ks++) {
            wmma::fragment<wmma::matrix_a, 16, 16, 16, __nv_bfloat16, wmma::row_major> ah[4], al[4];
            wmma::fragment<wmma::matrix_b, 16, 16, 16, __nv_bfloat16, wmma::row_major> bh[2], bl[2];
            #pragma unroll
            for (int m = 0; m < 4; m++) {
                int ro = (warp_m * 64 + m * 16) * SA + ks * 16;
                wmma::load_matrix_sync(ah[m], Ah_s + ro, SA);
                wmma::load_matrix_sync(al[m], Al_s + ro, SA);
            }
            #pragma unroll
            for (int n = 0; n < 2; n++) {
                int co = (ks * 16) * SW + warp_n * 32 + n * 16;
                wmma::load_matrix_sync(bh[n], Wh_s + co, SW);
                wmma::load_matrix_sync(bl[n], Wl_s + co, SW);
            }
            #pragma unroll
            for (int n = 0; n < 2; n++)
                #pragma unroll
                for (int m = 0; m < 4; m++) {
                    wmma::mma_sync(acc[m][n], ah[m], bh[n], acc[m][n]);
                    wmma::mma_sync(acc[m][n], al[m], bh[n], acc[m][n]);
                    wmma::mma_sync(acc[m][n], ah[m], bl[n], acc[m][n]);
                }
        }
        __syncthreads();
    }

    // ReLU elementwise on accumulators, store to padded global (no OOB possible)
    #pragma unroll
    for (int m = 0; m < 4; m++)
        #pragma unroll
        for (int n = 0; n < 2; n++) {
            #pragma unroll
            for (int e = 0; e < acc[m][n].num_elements; e++)
                acc[m][n].x[e] = fmaxf(acc[m][n].x[e], 0.0f);
            float* p = dst + (size_t)(row0 + warp_m * 64 + m * 16) * DD + warp_n * 32 + n * 16;
            wmma::store_matrix_sync(p, acc[m][n], DD, wmma::mem_row_major);
        }
}

// ---------------- finalize: copy valid rows to d_out + column sums -------------
__global__ void __launch_bounds__(256) k_finalize(float* __restrict__ out, int n) {
    __shared__ float4 s[8][32];
    int tid = threadIdx.x;
    int c = tid & 31;         // float4 column
    int rg = tid >> 5;        // 8 row groups
    int base = blockIdx.x * 128;
    float4 acc = make_float4(0.f, 0.f, 0.f, 0.f);
    const float4* __restrict__ h4 = (const float4*)g_hfin;
    float4* __restrict__ o4 = (float4*)out;
    #pragma unroll
    for (int i = 0; i < 16; i++) {
        int r = base + i * 8 + rg;
        if (r < n) {
            float4 v = h4[(size_t)r * 32 + c];
            o4[(size_t)r * 32 + c] = v;
            acc = f4_add(acc, v);
        }
    }
    s[rg][c] = acc;
    __syncthreads();
    if (rg == 0) {
        float4 t = s[0][c];
        #pragma unroll
        for (int k = 1; k < 8; k++) t = f4_add(t, s[k][c]);
        atomicAdd(&g_colsum[c * 4 + 0], t.x);
        atomicAdd(&g_colsum[c * 4 + 1], t.y);
        atomicAdd(&g_colsum[c * 4 + 2], t.z);
        atomicAdd(&g_colsum[c * 4 + 3], t.w);
    }
}

__global__ void k_mean(float* __restrict__ out_hg, float inv_n) {
    int i = threadIdx.x;
    if (i < DD) out_hg[i] = g_colsum[i] * inv_n;
}

// ---------------- launch ----------------
extern "C" void kernel_launch(void* const* d_in, const int* in_sizes, int n_in,
                              void* d_out, int out_size) {
    const float* feature = (const float*)d_in[0];
    const int*   src     = (const int*)d_in[1];
    const int*   dst     = (const int*)d_in[2];
    const float* W1 = (const float*)d_in[3];
    const float* b1 = (const float*)d_in[4];
    const float* W2 = (const float*)d_in[5];
    const float* b2 = (const float*)d_in[6];
    const float* W3 = (const float*)d_in[7];
    const float* b3 = (const float*)d_in[8];
    float* out = (float*)d_out;

    int N = in_sizes[0] / DD;   // 100000
    int E = in_sizes[1];        // 800000

    int gN     = (N + 255) / 256;
    int gE     = (E + 255) / 256;
    int nchunk = (N + 1023) / 1024;
    int gAgg   = (N * 32 + 255) / 256;   // one warp per node
    int gGemm  = (N + 127) / 128;        // 782
    int gSplit = (KEXT * DD + 255) / 256;

    // preprocessing
    k_zero<<<gN, 256>>>(N);
    k_degrees<<<gE, 256>>>(src, dst, E);
    k_norms<<<gN, 256>>>(N);
    k_scan_partial<<<nchunk, 1024>>>(N);
    k_scan_mid<<<1, 1>>>(nchunk, N);
    k_scan_final<<<nchunk, 1024>>>(N);
    k_csr_fill<<<gE, 256>>>(src, dst, E);

    // weight splits (hi/lo bf16, bias folded)
    k_split_w<<<gSplit, 256>>>(W1, b1, 0);
    k_split_w<<<gSplit, 256>>>(W2, b2, 1);
    k_split_w<<<gSplit, 256>>>(W3, b3, 2);

    // layer 1
    k_aggregate<<<gAgg, 256>>>((const float4*)feature, 1, N);
    k_gemm<<<gGemm, 256>>>(0, 0, N);
    // layer 2
    k_aggregate<<<gAgg, 256>>>(nullptr, 0, N);
    k_gemm<<<gGemm, 256>>>(1, 0, N);
    // layer 3
    k_aggregate<<<gAgg, 256>>>(nullptr, 0, N);
    k_gemm<<<gGemm, 256>>>(2, 1, N);

    // copy to d_out + readout
    k_finalize<<<gGemm, 256>>>(out, N);
    if (out_size >= N * DD + DD) {
        k_mean<<<1, 128>>>(out + (size_t)N * DD, 1.0f / (float)N);
    }
}

// round 12
// speedup vs baseline: 1.3461x; 1.3265x over previous
#include <cuda_runtime.h>
#include <cuda_bf16.h>
#include <cstdint>

#define NN 100000
#define NPAD 100096              // 782 * 128
#define EE 800000
#define DD 128

// ---------------- static device scratch (no allocations allowed) ----------------
__device__ float g_h[NPAD * DD];              // hidden node features (fp32)
__device__ __nv_bfloat16 g_Ahi[NPAD * DD];    // aggregated features, bf16 hi (pad rows stay 0)
__device__ __nv_bfloat16 g_Alo[NPAD * DD];    // aggregated features, bf16 residual
__device__ __nv_bfloat16 g_WThi[3 * DD * DD]; // per-layer W^T [n][k] bf16 hi
__device__ __nv_bfloat16 g_WTlo[3 * DD * DD]; // residuals
__device__ int   g_deg_out[NN];
__device__ int   g_deg_in[NN];
__device__ float g_norm_out[NN];
__device__ float g_norm_in[NN];
__device__ int   g_row_ptr[NN + 1];           // CSR by dst
__device__ int   g_fill[NN];
__device__ int   g_col[EE];                   // src index per CSR slot
__device__ int   g_part[256];                 // scan partials
__device__ float g_colsum[DD];                // column sums of final h (for mean)

// ---------------- small helpers ----------------
__device__ __forceinline__ void f4_fma(float4& acc, float4 v, float s) {
    acc.x = fmaf(v.x, s, acc.x);
    acc.y = fmaf(v.y, s, acc.y);
    acc.z = fmaf(v.z, s, acc.z);
    acc.w = fmaf(v.w, s, acc.w);
}
__device__ __forceinline__ float4 f4_add(float4 a, float4 b) {
    return make_float4(a.x + b.x, a.y + b.y, a.z + b.z, a.w + b.w);
}
__device__ __forceinline__ float4 f4_scale(float4 a, float s) {
    return make_float4(a.x * s, a.y * s, a.z * s, a.w * s);
}
__device__ __forceinline__ uint32_t smem_u32(const void* p) {
    uint32_t a;
    asm("{ .reg .u64 t; cvta.to.shared.u64 t, %1; cvt.u32.u64 %0, t; }" : "=r"(a) : "l"(p));
    return a;
}

// ---------------- sm_80-era tensor ops (valid on plain sm_100 target) ----------
#define LDSM4(r0, r1, r2, r3, addr) \
    asm volatile("ldmatrix.sync.aligned.m8n8.x4.shared.b16 {%0,%1,%2,%3}, [%4];" \
                 : "=r"(r0), "=r"(r1), "=r"(r2), "=r"(r3) : "r"(addr))
#define LDSM2(r0, r1, addr) \
    asm volatile("ldmatrix.sync.aligned.m8n8.x2.shared.b16 {%0,%1}, [%2];" \
                 : "=r"(r0), "=r"(r1) : "r"(addr))
#define MMA16816(c, a0, a1, a2, a3, b0, b1) \
    asm volatile("mma.sync.aligned.m16n8k16.row.col.f32.bf16.bf16.f32 " \
                 "{%0,%1,%2,%3}, {%4,%5,%6,%7}, {%8,%9}, {%0,%1,%2,%3};" \
                 : "+f"((c)[0]), "+f"((c)[1]), "+f"((c)[2]), "+f"((c)[3]) \
                 : "r"(a0), "r"(a1), "r"(a2), "r"(a3), "r"(b0), "r"(b1))

// swizzled offset inside a [128 rows x 128 bf16] tile (256B rows, 16B units):
// off = r*256 + ((c16 ^ (r&7))*16)  -> ldmatrix 8-row groups hit 8 distinct banks
__device__ __forceinline__ uint32_t tile_off(int r, int c16) {
    return ((uint32_t)r << 8) + (((uint32_t)(c16 ^ (r & 7))) << 4);
}

// ---------------- preprocessing kernels ----------------
__global__ void k_zero(int n) {
    int i = blockIdx.x * blockDim.x + threadIdx.x;
    if (i < n) { g_deg_out[i] = 0; g_deg_in[i] = 0; g_fill[i] = 0; }
    if (i < DD) g_colsum[i] = 0.0f;
}

__global__ void k_degrees(const int* __restrict__ src, const int* __restrict__ dst, int e) {
    int i = blockIdx.x * blockDim.x + threadIdx.x;
    if (i < e) {
        atomicAdd(&g_deg_out[src[i]], 1);
        atomicAdd(&g_deg_in[dst[i]], 1);
    }
}

__global__ void k_norms(int n) {
    int i = blockIdx.x * blockDim.x + threadIdx.x;
    if (i < n) {
        g_norm_out[i] = rsqrtf(fmaxf((float)g_deg_out[i], 1.0f));
        g_norm_in[i]  = rsqrtf(fmaxf((float)g_deg_in[i], 1.0f));
    }
}

__global__ void k_scan_partial(int n) {
    int idx = blockIdx.x * 1024 + threadIdx.x;
    int v = (idx < n) ? g_deg_in[idx] : 0;
    #pragma unroll
    for (int o = 16; o > 0; o >>= 1) v += __shfl_down_sync(0xFFFFFFFFu, v, o);
    __shared__ int ws[32];
    if ((threadIdx.x & 31) == 0) ws[threadIdx.x >> 5] = v;
    __syncthreads();
    if (threadIdx.x < 32) {
        int s = ws[threadIdx.x];
        #pragma unroll
        for (int o = 16; o > 0; o >>= 1) s += __shfl_down_sync(0xFFFFFFFFu, s, o);
        if (threadIdx.x == 0) g_part[blockIdx.x] = s;
    }
}

__global__ void k_scan_mid(int nchunk, int n) {
    int sum = 0;
    for (int i = 0; i < nchunk; i++) {
        int v = g_part[i];
        g_part[i] = sum;
        sum += v;
    }
    g_row_ptr[n] = sum;  // == E
}

__global__ void k_scan_final(int n) {
    int idx = blockIdx.x * 1024 + threadIdx.x;
    int v = (idx < n) ? g_deg_in[idx] : 0;
    int lane = threadIdx.x & 31, wid = threadIdx.x >> 5;
    int inc = v;
    #pragma unroll
    for (int o = 1; o < 32; o <<= 1) {
        int t = __shfl_up_sync(0xFFFFFFFFu, inc, o);
        if (lane >= o) inc += t;
    }
    __shared__ int ws[32];
    if (lane == 31) ws[wid] = inc;
    __syncthreads();
    if (wid == 0) {
        int s = ws[lane];
        #pragma unroll
        for (int o = 1; o < 32; o <<= 1) {
            int t = __shfl_up_sync(0xFFFFFFFFu, s, o);
            if (lane >= o) s += t;
        }
        ws[lane] = s;
    }
    __syncthreads();
    int add = (wid > 0) ? ws[wid - 1] : 0;
    if (idx < n) g_row_ptr[idx] = (inc - v) + add + g_part[blockIdx.x];
}

__global__ void k_csr_fill(const int* __restrict__ src, const int* __restrict__ dst, int e) {
    int i = blockIdx.x * blockDim.x + threadIdx.x;
    if (i < e) {
        int d = dst[i];
        int pos = g_row_ptr[d] + atomicAdd(&g_fill[d], 1);
        g_col[pos] = src[i];
    }
}

// W split+transpose: fp32 W[k][n] -> bf16 hi/lo W^T[n][k]
__global__ void k_split_w(const float* __restrict__ W, int lay) {
    int i = blockIdx.x * blockDim.x + threadIdx.x;
    if (i >= DD * DD) return;
    int k = i / DD, n = i % DD;
    float w = W[i];
    __nv_bfloat16 hi = __float2bfloat16(w);
    __nv_bfloat16 lo = __float2bfloat16(w - __bfloat162float(hi));
    size_t o = (size_t)lay * DD * DD + (size_t)n * DD + k;
    g_WThi[o] = hi;
    g_WTlo[o] = lo;
}

// ---------------- aggregation: one warp per node (gather, no float atomics) ----
__global__ void __launch_bounds__(256) k_aggregate(const float4* __restrict__ in, int use_in, int n) {
    int warp = (blockIdx.x * blockDim.x + threadIdx.x) >> 5;
    int lane = threadIdx.x & 31;
    if (warp >= n) return;
    const float4* __restrict__ feat4 = use_in ? in : (const float4*)g_h;
    int beg = g_row_ptr[warp];
    int end = g_row_ptr[warp + 1];
    float4 acc = make_float4(0.f, 0.f, 0.f, 0.f);
    int e = beg;
    for (; e + 4 <= end; e += 4) {
        int s0 = g_col[e], s1 = g_col[e + 1], s2 = g_col[e + 2], s3 = g_col[e + 3];
        float n0 = g_norm_out[s0], n1 = g_norm_out[s1];
        float n2 = g_norm_out[s2], n3 = g_norm_out[s3];
        float4 v0 = feat4[(size_t)s0 * 32 + lane];
        float4 v1 = feat4[(size_t)s1 * 32 + lane];
        float4 v2 = feat4[(size_t)s2 * 32 + lane];
        float4 v3 = feat4[(size_t)s3 * 32 + lane];
        f4_fma(acc, v0, n0);
        f4_fma(acc, v1, n1);
        f4_fma(acc, v2, n2);
        f4_fma(acc, v3, n3);
    }
    for (; e < end; e++) {
        int s = g_col[e];
        f4_fma(acc, feat4[(size_t)s * 32 + lane], g_norm_out[s]);
    }
    float4 r = f4_scale(acc, g_norm_in[warp]);

    __nv_bfloat16 a0 = __float2bfloat16(r.x), a1 = __float2bfloat16(r.y);
    __nv_bfloat16 a2 = __float2bfloat16(r.z), a3 = __float2bfloat16(r.w);
    __nv_bfloat16 l0 = __float2bfloat16(r.x - __bfloat162float(a0));
    __nv_bfloat16 l1 = __float2bfloat16(r.y - __bfloat162float(a1));
    __nv_bfloat16 l2 = __float2bfloat16(r.z - __bfloat162float(a2));
    __nv_bfloat16 l3 = __float2bfloat16(r.w - __bfloat162float(a3));
    size_t base = (size_t)warp * DD + lane * 4;
    __nv_bfloat162 h01, h23, q01, q23;
    h01.x = a0; h01.y = a1; h23.x = a2; h23.y = a3;
    q01.x = l0; q01.y = l1; q23.x = l2; q23.y = l3;
    *(__nv_bfloat162*)(g_Ahi + base)     = h01;
    *(__nv_bfloat162*)(g_Ahi + base + 2) = h23;
    *(__nv_bfloat162*)(g_Alo + base)     = q01;
    *(__nv_bfloat162*)(g_Alo + base + 2) = q23;
}

// ---------------- GEMM via ldmatrix + mma.sync bf16-split ----------------------
// Block 128x128xK128, 512 threads = 16 warps (4m x 4n), warp tile 32x32.
// D = Ah·Wh + Al·Wh + Ah·Wl (fp32 acc; missing Al·Wl ~ 2^-18 relative).
// smem: 4 swizzled [128x128 bf16] tiles = 128KB dynamic, 1 CTA/SM.
#define SM_AH 0
#define SM_AL 32768
#define SM_WH 65536
#define SM_WL 98304
#define SM_TOT 131072

__global__ void __launch_bounds__(512, 1) k_gemm(
    int lay, const float* __restrict__ bias, float* __restrict__ out, int last, int M)
{
    extern __shared__ __align__(16) char smem[];
    uint32_t sb = smem_u32(smem);
    int tid = threadIdx.x;
    int wid = tid >> 5, lane = tid & 31;
    int row0 = blockIdx.x * 128;

    // ---- stage 4 tiles (each thread: 4 x 16B per tile) ----
    {
        const __nv_bfloat16* __restrict__ wh = g_WThi + (size_t)lay * DD * DD;
        const __nv_bfloat16* __restrict__ wl = g_WTlo + (size_t)lay * DD * DD;
        #pragma unroll
        for (int t = 0; t < 4; t++) {
            int i = tid + t * 512;           // 0..2047
            int r = i >> 4, c16 = i & 15;
            uint32_t off = tile_off(r, c16);
            size_t ga = (size_t)(row0 + r) * DD + c16 * 8;
            size_t gw = (size_t)r * DD + c16 * 8;
            *(uint4*)(smem + SM_AH + off) = *(const uint4*)(g_Ahi + ga);
            *(uint4*)(smem + SM_AL + off) = *(const uint4*)(g_Alo + ga);
            *(uint4*)(smem + SM_WH + off) = *(const uint4*)(wh + gw);
            *(uint4*)(smem + SM_WL + off) = *(const uint4*)(wl + gw);
        }
    }
    __syncthreads();

    int wm = wid & 3, wn = wid >> 2;         // 4x4 warp grid
    int m_base = wm * 32, n_base = wn * 32;

    float acc[2][4][4];
    #pragma unroll
    for (int mt = 0; mt < 2; mt++)
        #pragma unroll
        for (int nt = 0; nt < 4; nt++)
            #pragma unroll
            for (int e = 0; e < 4; e++) acc[mt][nt][e] = 0.0f;

    // per-thread ldmatrix row indices
    int arow0 = m_base + (lane & 15);        // + mt*16
    int brow  = n_base + (lane & 7);         // + nt*8
    uint32_t sa = sb + SM_AH;
    uint32_t sw = sb + SM_WH;

    #pragma unroll
    for (int ks = 0; ks < 8; ks++) {
        int c16a = ks * 2 + (lane >> 4);          // A: lanes 16-31 take k0+8
        int c16b = ks * 2 + ((lane >> 3) & 1);    // B: lanes 8-15 take k0+8

        uint32_t ah[2][4], al[2][4];
        #pragma unroll
        for (int mt = 0; mt < 2; mt++) {
            int r = arow0 + mt * 16;
            uint32_t adr = sa + tile_off(r, c16a);
            LDSM4(ah[mt][0], ah[mt][1], ah[mt][2], ah[mt][3], adr);
            LDSM4(al[mt][0], al[mt][1], al[mt][2], al[mt][3], adr + 32768u);
        }
        uint32_t bh[4][2], bl[4][2];
        #pragma unroll
        for (int nt = 0; nt < 4; nt++) {
            int r = brow + nt * 8;
            uint32_t adr = sw + tile_off(r, c16b);
            LDSM2(bh[nt][0], bh[nt][1], adr);
            LDSM2(bl[nt][0], bl[nt][1], adr + 32768u);
        }
        #pragma unroll
        for (int mt = 0; mt < 2; mt++)
            #pragma unroll
            for (int nt = 0; nt < 4; nt++) {
                MMA16816(acc[mt][nt], ah[mt][0], ah[mt][1], ah[mt][2], ah[mt][3],
                         bh[nt][0], bh[nt][1]);
                MMA16816(acc[mt][nt], al[mt][0], al[mt][1], al[mt][2], al[mt][3],
                         bh[nt][0], bh[nt][1]);
                MMA16816(acc[mt][nt], ah[mt][0], ah[mt][1], ah[mt][2], ah[mt][3],
                         bl[nt][0], bl[nt][1]);
            }
    }

    // ---- epilogue: relu(acc + bias) -> dst (float2 per fragment row) ----
    float* __restrict__ dst = last ? out : g_h;
    int group = lane >> 2, tid4 = lane & 3;
    #pragma unroll
    for (int mt = 0; mt < 2; mt++) {
        #pragma unroll
        for (int nt = 0; nt < 4; nt++) {
            int col = n_base + nt * 8 + tid4 * 2;
            float2 bv = *(const float2*)(bias + col);
            int r1 = row0 + m_base + mt * 16 + group;
            int r2 = r1 + 8;
            float2 v1, v2;
            v1.x = fmaxf(acc[mt][nt][0] + bv.x, 0.f);
            v1.y = fmaxf(acc[mt][nt][1] + bv.y, 0.f);
            v2.x = fmaxf(acc[mt][nt][2] + bv.x, 0.f);
            v2.y = fmaxf(acc[mt][nt][3] + bv.y, 0.f);
            if (!last || r1 < M) *(float2*)(dst + (size_t)r1 * DD + col) = v1;
            if (!last || r2 < M) *(float2*)(dst + (size_t)r2 * DD + col) = v2;
        }
    }
}

// ---------------- colsum over final output + mean ------------------------------
__global__ void __launch_bounds__(256) k_colsum(const float* __restrict__ out, int n) {
    __shared__ float4 s[8][32];
    int tid = threadIdx.x;
    int c = tid & 31;         // float4 column
    int rg = tid >> 5;        // 8 row groups
    int base = blockIdx.x * 128;
    float4 acc = make_float4(0.f, 0.f, 0.f, 0.f);
    const float4* __restrict__ h4 = (const float4*)out;
    #pragma unroll
    for (int i = 0; i < 16; i++) {
        int r = base + i * 8 + rg;
        if (r < n) acc = f4_add(acc, h4[(size_t)r * 32 + c]);
    }
    s[rg][c] = acc;
    __syncthreads();
    if (rg == 0) {
        float4 t = s[0][c];
        #pragma unroll
        for (int k = 1; k < 8; k++) t = f4_add(t, s[k][c]);
        atomicAdd(&g_colsum[c * 4 + 0], t.x);
        atomicAdd(&g_colsum[c * 4 + 1], t.y);
        atomicAdd(&g_colsum[c * 4 + 2], t.z);
        atomicAdd(&g_colsum[c * 4 + 3], t.w);
    }
}

__global__ void k_mean(float* __restrict__ out_hg, float inv_n) {
    int i = threadIdx.x;
    if (i < DD) out_hg[i] = g_colsum[i] * inv_n;
}

// ---------------- launch ----------------
extern "C" void kernel_launch(void* const* d_in, const int* in_sizes, int n_in,
                              void* d_out, int out_size) {
    const float* feature = (const float*)d_in[0];
    const int*   src     = (const int*)d_in[1];
    const int*   dst     = (const int*)d_in[2];
    const float* W1 = (const float*)d_in[3];
    const float* b1 = (const float*)d_in[4];
    const float* W2 = (const float*)d_in[5];
    const float* b2 = (const float*)d_in[6];
    const float* W3 = (const float*)d_in[7];
    const float* b3 = (const float*)d_in[8];
    float* out = (float*)d_out;

    int N = in_sizes[0] / DD;   // 100000
    int E = in_sizes[1];        // 800000

    int gN     = (N + 255) / 256;
    int gE     = (E + 255) / 256;
    int nchunk = (N + 1023) / 1024;
    int gAgg   = (N * 32 + 255) / 256;   // one warp per node
    int gGemm  = (N + 127) / 128;        // 782
    int gSplit = (DD * DD + 255) / 256;

    // >48KB dynamic smem needs the attribute (host-side, capture-safe, no alloc)
    cudaFuncSetAttribute(k_gemm, cudaFuncAttributeMaxDynamicSharedMemorySize, SM_TOT);

    // preprocessing
    k_zero<<<gN, 256>>>(N);
    k_degrees<<<gE, 256>>>(src, dst, E);
    k_norms<<<gN, 256>>>(N);
    k_scan_partial<<<nchunk, 1024>>>(N);
    k_scan_mid<<<1, 1>>>(nchunk, N);
    k_scan_final<<<nchunk, 1024>>>(N);
    k_csr_fill<<<gE, 256>>>(src, dst, E);

    // weight split + transpose
    k_split_w<<<gSplit, 256>>>(W1, 0);
    k_split_w<<<gSplit, 256>>>(W2, 1);
    k_split_w<<<gSplit, 256>>>(W3, 2);

    // layer 1
    k_aggregate<<<gAgg, 256>>>((const float4*)feature, 1, N);
    k_gemm<<<gGemm, 512, SM_TOT>>>(0, b1, nullptr, 0, N);
    // layer 2
    k_aggregate<<<gAgg, 256>>>(nullptr, 0, N);
    k_gemm<<<gGemm, 512, SM_TOT>>>(1, b2, nullptr, 0, N);
    // layer 3 -> d_out directly
    k_aggregate<<<gAgg, 256>>>(nullptr, 0, N);
    k_gemm<<<gGemm, 512, SM_TOT>>>(2, b3, out, 1, N);

    // readout
    k_colsum<<<gGemm, 256>>>(out, N);
    if (out_size >= N * DD + DD) {
        k_mean<<<1, 128>>>(out + (size_t)N * DD, 1.0f / (float)N);
    }
}